// round 15
// baseline (speedup 1.0000x reference)
#include <cuda_runtime.h>
#include <stdint.h>

// Output: [B, C, X, Y] fp32
#define BB 4
#define CC 256
#define XX 256
#define YY 256
#define XY (XX * YY)

// Inverse index: dense cell (b,x,y) -> (feature row + 1), 0 = empty. 1 MB.
// Zero-initialized at module load; the LAST sibling gather block of each
// (b,x) row zeroes its slice again at kernel end, so every launch starts
// from all-zero state. d_cnt likewise returns to zero every launch.
__device__ int d_inv[BB * XX * YY];
__device__ int d_cnt[BB * XX];

// ---------------------------------------------------------------------------
// Kernel 1: scatter (row index + 1) into d_inv. Bounds-guarded = mode="drop".
// One thread = 4 points via 3 independent int4 loads (no smem staging, no
// sync): maximum memory-level parallelism, shortest critical path.
// (R14-measured best aux configuration.)
// ---------------------------------------------------------------------------
__global__ void __launch_bounds__(256)
build_inv_kernel(const int* __restrict__ coords, int n) {
    const int t  = blockIdx.x * blockDim.x + threadIdx.x;
    const int p0 = t << 2;               // first point of this thread
    if (p0 >= n) return;

    // 3 int4 = 12 ints = 4 points, issued back-to-back (independent).
    const int4* c4 = reinterpret_cast<const int4*>(coords) + 3 * t;
    int4 a, bq, cq;
    if (p0 + 4 <= n) {                   // fast path: full vector loads
        a  = c4[0];
        bq = c4[1];
        cq = c4[2];
    } else {                             // tail: scalar-safe
        int tmp[12];
        #pragma unroll
        for (int k = 0; k < 12; k++) {
            const int idx = 12 * t + k;
            tmp[k] = (idx < 3 * n) ? coords[idx] : -1;
        }
        a  = make_int4(tmp[0], tmp[1], tmp[2],  tmp[3]);
        bq = make_int4(tmp[4], tmp[5], tmp[6],  tmp[7]);
        cq = make_int4(tmp[8], tmp[9], tmp[10], tmp[11]);
    }

    const int pb[4] = {a.x,  a.w,  bq.z, cq.y};   // b of points 0..3
    const int px[4] = {a.y,  bq.x, bq.w, cq.z};   // x
    const int py[4] = {a.z,  bq.y, cq.x, cq.w};   // y

    #pragma unroll
    for (int e = 0; e < 4; e++) {
        const int p = p0 + e;
        if (p < n) {
            const int b = pb[e], x = px[e], y = py[e];
            if ((unsigned)b < BB && (unsigned)x < XX && (unsigned)y < YY) {
                d_inv[(b * XX + x) * YY + y] = p + 1;
            }
        }
    }
}

// ---------------------------------------------------------------------------
// Kernel 2: wide row-locality gather with fused inv reset — the measured
// best configuration (R12: 73.3 us, DRAM 71.8%), __stcs restored.
//
// One block = 512 threads: ALL 256 y cells of one (b,x) row x 64 channels
// (cg fastest -> 4 co-resident siblings cluster reads of each feats row as
// 4 x 256 B chunks). Each block writes 1 KB contiguous per channel plane
// with streaming STG.128 (evict-first: write-once surface stays out of L2).
// Tile float4[256][16] (64 KB dynamic), column swizzle q ^ ((j>>2) & 15):
// conflict-free in the cp.async fill and the store-phase transpose reads.
// Reset: 4th-arriving sibling zeroes the 256-entry inv slice + counter.
// ---------------------------------------------------------------------------
__global__ void __launch_bounds__(512)
gather_kernel(const float* __restrict__ feats, float* __restrict__ out) {
    __shared__ int s_inv[YY];
    __shared__ int s_last;
    extern __shared__ float4 tile4[];    // [256 * 16] = 64 KB

    const int cg = blockIdx.x & 3;       // 64-channel group
    const int bx = blockIdx.x >> 2;      // b*256 + x
    const int b  = bx >> 8;
    const int x  = bx & 255;
    const int L  = bx * YY;              // linear cell base of this (b,x) row

    const int tid = threadIdx.x;

    // Stage this row's inverse indices (shared by the 4 sibling blocks).
    if (tid < YY) s_inv[tid] = d_inv[L + tid];
    __syncthreads();                     // all inv loads of this block done

    if (tid == 0) {
        s_last = (atomicAdd(&d_cnt[bx], 1) == 3) ? 1 : 0;
    }

    // ---- load phase: 8 independent cp.async per thread ----
    const int q  = tid & 15;             // 16 B chunk within 256 B
    const int jb = tid >> 4;             // 0..31: cell within wave
    const int csrc = cg * 64 + (q << 2); // first channel of this chunk

    #pragma unroll
    for (int wave = 0; wave < 8; wave++) {
        const int j = (wave << 5) + jb;  // y cell 0..255
        const int r = s_inv[j];
        const float* src = r ? feats + (size_t)(r - 1) * CC + csrc
                             : feats;    // valid addr even when size==0
        const int size = r ? 16 : 0;     // 0 -> zero-fill 16 B
        const uint32_t dst = (uint32_t)__cvta_generic_to_shared(
            &tile4[(j << 4) + (q ^ ((j >> 2) & 15))]);
        asm volatile("cp.async.cg.shared.global [%0], [%1], 16, %2;"
                     :: "r"(dst), "l"(src), "r"(size));
    }
    asm volatile("cp.async.commit_group;");
    asm volatile("cp.async.wait_group 0;");
    __syncthreads();                     // tile ready; s_last visible

    // ---- store phase: 1 KB contiguous per channel, streaming STG.128 ----
    const int w  = tid >> 5;             // warp 0..15 -> channels 4w..4w+3
    const int l  = tid & 31;
    const int l7 = l & 7;
    const int l3 = l >> 3;

    const float* tf = reinterpret_cast<const float*>(tile4);
    float* op = out + ((size_t)b * CC + cg * 64 + (w << 2) + l3) * XY
                    + (size_t)x * YY;

    #pragma unroll
    for (int i = 0; i < 8; i++) {
        const int s    = ((i << 3) + l7) & 15;       // (8i + l7) & 15
        const int colf = ((w ^ s) << 2) + l3;        // float col in 256 B row
        const int jbase = (i << 5) + (l7 << 2);      // y = 32i + 4*l7
        float4 v;
        v.x = tf[(jbase + 0) * 64 + colf];
        v.y = tf[(jbase + 1) * 64 + colf];
        v.z = tf[(jbase + 2) * 64 + colf];
        v.w = tf[(jbase + 3) * 64 + colf];
        __stcs(reinterpret_cast<float4*>(op + jbase), v);
    }

    // ---- fused reset: last sibling restores inv slice + counter to 0 ----
    if (s_last) {
        if (tid < YY) d_inv[L + tid] = 0;
        if (tid == 0) d_cnt[bx] = 0;
    }
}

// ---------------------------------------------------------------------------
// Launcher
// ---------------------------------------------------------------------------
extern "C" void kernel_launch(void* const* d_in, const int* in_sizes, int n_in,
                              void* d_out, int out_size) {
    const float* feats  = (const float*)d_in[0];
    const int*   coords = (const int*)d_in[1];
    float*       out    = (float*)d_out;

    const int n = in_sizes[1] / 3;  // number of sparse points

    const int smem = 256 * 16 * sizeof(float4);   // 64 KB dynamic tile
    cudaFuncSetAttribute(gather_kernel,
                         cudaFuncAttributeMaxDynamicSharedMemorySize, smem);

    build_inv_kernel<<<((n + 3) / 4 + 255) / 256, 256>>>(coords, n);
    gather_kernel<<<BB * XX * 4, 512, smem>>>(feats, out);
}

// round 16
// speedup vs baseline: 1.0019x; 1.0019x over previous
#include <cuda_runtime.h>
#include <stdint.h>

// Output: [B, C, X, Y] fp32
#define BB 4
#define CC 256
#define XX 256
#define YY 256
#define XY (XX * YY)

// Inverse index: dense cell (b,x,y) -> (feature row + 1), 0 = empty. 1 MB.
// Zero-initialized at module load; the LAST sibling gather block of each
// (b,x) row zeroes its slice again at kernel end, so every launch starts
// from all-zero state. d_cnt likewise returns to zero every launch.
__device__ int d_inv[BB * XX * YY];
__device__ int d_cnt[BB * XX];

// ---------------------------------------------------------------------------
// Kernel 1: scatter (row index + 1) into d_inv. Bounds-guarded = mode="drop".
// One thread = 4 points via 3 independent int4 loads (no smem staging, no
// sync): maximum memory-level parallelism, shortest critical path.
// ---------------------------------------------------------------------------
__global__ void __launch_bounds__(256)
build_inv_kernel(const int* __restrict__ coords, int n) {
    const int t  = blockIdx.x * blockDim.x + threadIdx.x;
    const int p0 = t << 2;               // first point of this thread
    if (p0 >= n) return;

    // 3 int4 = 12 ints = 4 points, issued back-to-back (independent).
    const int4* c4 = reinterpret_cast<const int4*>(coords) + 3 * t;
    int4 a, bq, cq;
    if (p0 + 4 <= n) {                   // fast path: full vector loads
        a  = c4[0];
        bq = c4[1];
        cq = c4[2];
    } else {                             // tail: scalar-safe
        int tmp[12];
        #pragma unroll
        for (int k = 0; k < 12; k++) {
            const int idx = 12 * t + k;
            tmp[k] = (idx < 3 * n) ? coords[idx] : -1;
        }
        a  = make_int4(tmp[0], tmp[1], tmp[2],  tmp[3]);
        bq = make_int4(tmp[4], tmp[5], tmp[6],  tmp[7]);
        cq = make_int4(tmp[8], tmp[9], tmp[10], tmp[11]);
    }

    const int pb[4] = {a.x,  a.w,  bq.z, cq.y};   // b of points 0..3
    const int px[4] = {a.y,  bq.x, bq.w, cq.z};   // x
    const int py[4] = {a.z,  bq.y, cq.x, cq.w};   // y

    #pragma unroll
    for (int e = 0; e < 4; e++) {
        const int p = p0 + e;
        if (p < n) {
            const int b = pb[e], x = px[e], y = py[e];
            if ((unsigned)b < BB && (unsigned)x < XX && (unsigned)y < YY) {
                d_inv[(b * XX + x) * YY + y] = p + 1;
            }
        }
    }
}

// ---------------------------------------------------------------------------
// Kernel 2: wide row-locality gather with fused inv reset (best-measured
// total configuration, R14: 81.98 us end-to-end).
//
// One block = 512 threads: ALL 256 y cells of one (b,x) row x 64 channels
// (cg fastest -> 4 co-resident siblings cluster reads of each feats row as
// 4 x 256 B chunks). Each block writes 1 KB contiguous per channel plane —
// the DRAM row-locality structure that produced the only decisive win of
// the series (113 -> 82 us).
// Tile float4[256][16] (64 KB dynamic), column swizzle q ^ ((j>>2) & 15):
// conflict-free in the cp.async fill and the store-phase transpose reads.
// Reset: 4th-arriving sibling zeroes the 256-entry inv slice + counter.
// Every output element is written exactly once (zero-fill for empty cells
// via cp.async src-size 0), so the poisoned output is fully initialized.
// ---------------------------------------------------------------------------
__global__ void __launch_bounds__(512)
gather_kernel(const float* __restrict__ feats, float* __restrict__ out) {
    __shared__ int s_inv[YY];
    __shared__ int s_last;
    extern __shared__ float4 tile4[];    // [256 * 16] = 64 KB

    const int cg = blockIdx.x & 3;       // 64-channel group
    const int bx = blockIdx.x >> 2;      // b*256 + x
    const int b  = bx >> 8;
    const int x  = bx & 255;
    const int L  = bx * YY;              // linear cell base of this (b,x) row

    const int tid = threadIdx.x;

    // Stage this row's inverse indices (shared by the 4 sibling blocks).
    if (tid < YY) s_inv[tid] = d_inv[L + tid];
    __syncthreads();                     // all inv loads of this block done

    if (tid == 0) {
        s_last = (atomicAdd(&d_cnt[bx], 1) == 3) ? 1 : 0;
    }

    // ---- load phase: 8 independent cp.async per thread ----
    const int q  = tid & 15;             // 16 B chunk within 256 B
    const int jb = tid >> 4;             // 0..31: cell within wave
    const int csrc = cg * 64 + (q << 2); // first channel of this chunk

    #pragma unroll
    for (int wave = 0; wave < 8; wave++) {
        const int j = (wave << 5) + jb;  // y cell 0..255
        const int r = s_inv[j];
        const float* src = r ? feats + (size_t)(r - 1) * CC + csrc
                             : feats;    // valid addr even when size==0
        const int size = r ? 16 : 0;     // 0 -> zero-fill 16 B
        const uint32_t dst = (uint32_t)__cvta_generic_to_shared(
            &tile4[(j << 4) + (q ^ ((j >> 2) & 15))]);
        asm volatile("cp.async.cg.shared.global [%0], [%1], 16, %2;"
                     :: "r"(dst), "l"(src), "r"(size));
    }
    asm volatile("cp.async.commit_group;");
    asm volatile("cp.async.wait_group 0;");
    __syncthreads();                     // tile ready; s_last visible

    // ---- store phase: 1 KB contiguous per channel, STG.128 full lines ----
    const int w  = tid >> 5;             // warp 0..15 -> channels 4w..4w+3
    const int l  = tid & 31;
    const int l7 = l & 7;
    const int l3 = l >> 3;

    const float* tf = reinterpret_cast<const float*>(tile4);
    float* op = out + ((size_t)b * CC + cg * 64 + (w << 2) + l3) * XY
                    + (size_t)x * YY;

    #pragma unroll
    for (int i = 0; i < 8; i++) {
        const int s    = ((i << 3) + l7) & 15;       // (8i + l7) & 15
        const int colf = ((w ^ s) << 2) + l3;        // float col in 256 B row
        const int jbase = (i << 5) + (l7 << 2);      // y = 32i + 4*l7
        float4 v;
        v.x = tf[(jbase + 0) * 64 + colf];
        v.y = tf[(jbase + 1) * 64 + colf];
        v.z = tf[(jbase + 2) * 64 + colf];
        v.w = tf[(jbase + 3) * 64 + colf];
        *reinterpret_cast<float4*>(op + jbase) = v;  // STG.128
    }

    // ---- fused reset: last sibling restores inv slice + counter to 0 ----
    if (s_last) {
        if (tid < YY) d_inv[L + tid] = 0;
        if (tid == 0) d_cnt[bx] = 0;
    }
}

// ---------------------------------------------------------------------------
// Launcher
// ---------------------------------------------------------------------------
extern "C" void kernel_launch(void* const* d_in, const int* in_sizes, int n_in,
                              void* d_out, int out_size) {
    const float* feats  = (const float*)d_in[0];
    const int*   coords = (const int*)d_in[1];
    float*       out    = (float*)d_out;

    const int n = in_sizes[1] / 3;  // number of sparse points

    const int smem = 256 * 16 * sizeof(float4);   // 64 KB dynamic tile
    cudaFuncSetAttribute(gather_kernel,
                         cudaFuncAttributeMaxDynamicSharedMemorySize, smem);

    build_inv_kernel<<<((n + 3) / 4 + 255) / 256, 256>>>(coords, n);
    gather_kernel<<<BB * XX * 4, 512, smem>>>(feats, out);
}

// round 17
// speedup vs baseline: 1.0055x; 1.0035x over previous
#include <cuda_runtime.h>
#include <stdint.h>

// Output: [B, C, X, Y] fp32
#define BB 4
#define CC 256
#define XX 256
#define YY 256
#define XY (XX * YY)

// Inverse index: dense cell (b,x,y) -> (feature row + 1), 0 = empty. 1 MB.
// Zero-initialized at module load; the LAST sibling gather block of each
// (b,x) row zeroes its slice again at kernel end, so every launch starts
// from all-zero state. d_cnt likewise returns to zero every launch.
__device__ int d_inv[BB * XX * YY];
__device__ int d_cnt[BB * XX];

// ---------------------------------------------------------------------------
// Kernel 1: scatter (row index + 1) into d_inv. Bounds-guarded = mode="drop".
// One thread = 4 points via 3 independent int4 loads (no smem staging, no
// sync): maximum memory-level parallelism, shortest critical path.
// ---------------------------------------------------------------------------
__global__ void __launch_bounds__(256)
build_inv_kernel(const int* __restrict__ coords, int n) {
    const int t  = blockIdx.x * blockDim.x + threadIdx.x;
    const int p0 = t << 2;               // first point of this thread
    if (p0 >= n) return;

    // 3 int4 = 12 ints = 4 points, issued back-to-back (independent).
    const int4* c4 = reinterpret_cast<const int4*>(coords) + 3 * t;
    int4 a, bq, cq;
    if (p0 + 4 <= n) {                   // fast path: full vector loads
        a  = c4[0];
        bq = c4[1];
        cq = c4[2];
    } else {                             // tail: scalar-safe
        int tmp[12];
        #pragma unroll
        for (int k = 0; k < 12; k++) {
            const int idx = 12 * t + k;
            tmp[k] = (idx < 3 * n) ? coords[idx] : -1;
        }
        a  = make_int4(tmp[0], tmp[1], tmp[2],  tmp[3]);
        bq = make_int4(tmp[4], tmp[5], tmp[6],  tmp[7]);
        cq = make_int4(tmp[8], tmp[9], tmp[10], tmp[11]);
    }

    const int pb[4] = {a.x,  a.w,  bq.z, cq.y};   // b of points 0..3
    const int px[4] = {a.y,  bq.x, bq.w, cq.z};   // x
    const int py[4] = {a.z,  bq.y, cq.x, cq.w};   // y

    #pragma unroll
    for (int e = 0; e < 4; e++) {
        const int p = p0 + e;
        if (p < n) {
            const int b = pb[e], x = px[e], y = py[e];
            if ((unsigned)b < BB && (unsigned)x < XX && (unsigned)y < YY) {
                d_inv[(b * XX + x) * YY + y] = p + 1;
            }
        }
    }
}

// ---------------------------------------------------------------------------
// Kernel 2: wide row-locality gather with fused inv reset (best-measured
// configuration), with WRITE-THROUGH stores (__stwt) as the final store-path
// probe: no dirty L2 state -> no writeback bursts contending with the read
// stream at the LTS/DRAM scheduler.
//
// One block = 512 threads: ALL 256 y cells of one (b,x) row x 64 channels
// (cg fastest -> 4 co-resident siblings cluster reads of each feats row as
// 4 x 256 B chunks). Each block writes 1 KB contiguous per channel plane —
// the DRAM row-locality structure that produced the series' decisive win.
// Tile float4[256][16] (64 KB dynamic), column swizzle q ^ ((j>>2) & 15):
// conflict-free in the cp.async fill and the store-phase transpose reads.
// Reset: 4th-arriving sibling zeroes the 256-entry inv slice + counter.
// Every output element is written exactly once (zero-fill for empty cells
// via cp.async src-size 0), so the poisoned output is fully initialized.
// ---------------------------------------------------------------------------
__global__ void __launch_bounds__(512)
gather_kernel(const float* __restrict__ feats, float* __restrict__ out) {
    __shared__ int s_inv[YY];
    __shared__ int s_last;
    extern __shared__ float4 tile4[];    // [256 * 16] = 64 KB

    const int cg = blockIdx.x & 3;       // 64-channel group
    const int bx = blockIdx.x >> 2;      // b*256 + x
    const int b  = bx >> 8;
    const int x  = bx & 255;
    const int L  = bx * YY;              // linear cell base of this (b,x) row

    const int tid = threadIdx.x;

    // Stage this row's inverse indices (shared by the 4 sibling blocks).
    if (tid < YY) s_inv[tid] = d_inv[L + tid];
    __syncthreads();                     // all inv loads of this block done

    if (tid == 0) {
        s_last = (atomicAdd(&d_cnt[bx], 1) == 3) ? 1 : 0;
    }

    // ---- load phase: 8 independent cp.async per thread ----
    const int q  = tid & 15;             // 16 B chunk within 256 B
    const int jb = tid >> 4;             // 0..31: cell within wave
    const int csrc = cg * 64 + (q << 2); // first channel of this chunk

    #pragma unroll
    for (int wave = 0; wave < 8; wave++) {
        const int j = (wave << 5) + jb;  // y cell 0..255
        const int r = s_inv[j];
        const float* src = r ? feats + (size_t)(r - 1) * CC + csrc
                             : feats;    // valid addr even when size==0
        const int size = r ? 16 : 0;     // 0 -> zero-fill 16 B
        const uint32_t dst = (uint32_t)__cvta_generic_to_shared(
            &tile4[(j << 4) + (q ^ ((j >> 2) & 15))]);
        asm volatile("cp.async.cg.shared.global [%0], [%1], 16, %2;"
                     :: "r"(dst), "l"(src), "r"(size));
    }
    asm volatile("cp.async.commit_group;");
    asm volatile("cp.async.wait_group 0;");
    __syncthreads();                     // tile ready; s_last visible

    // ---- store phase: 1 KB contiguous per channel, write-through STG.128 --
    const int w  = tid >> 5;             // warp 0..15 -> channels 4w..4w+3
    const int l  = tid & 31;
    const int l7 = l & 7;
    const int l3 = l >> 3;

    const float* tf = reinterpret_cast<const float*>(tile4);
    float* op = out + ((size_t)b * CC + cg * 64 + (w << 2) + l3) * XY
                    + (size_t)x * YY;

    #pragma unroll
    for (int i = 0; i < 8; i++) {
        const int s    = ((i << 3) + l7) & 15;       // (8i + l7) & 15
        const int colf = ((w ^ s) << 2) + l3;        // float col in 256 B row
        const int jbase = (i << 5) + (l7 << 2);      // y = 32i + 4*l7
        float4 v;
        v.x = tf[(jbase + 0) * 64 + colf];
        v.y = tf[(jbase + 1) * 64 + colf];
        v.z = tf[(jbase + 2) * 64 + colf];
        v.w = tf[(jbase + 3) * 64 + colf];
        __stwt(reinterpret_cast<float4*>(op + jbase), v);  // write-through
    }

    // ---- fused reset: last sibling restores inv slice + counter to 0 ----
    if (s_last) {
        if (tid < YY) d_inv[L + tid] = 0;
        if (tid == 0) d_cnt[bx] = 0;
    }
}

// ---------------------------------------------------------------------------
// Launcher
// ---------------------------------------------------------------------------
extern "C" void kernel_launch(void* const* d_in, const int* in_sizes, int n_in,
                              void* d_out, int out_size) {
    const float* feats  = (const float*)d_in[0];
    const int*   coords = (const int*)d_in[1];
    float*       out    = (float*)d_out;

    const int n = in_sizes[1] / 3;  // number of sparse points

    const int smem = 256 * 16 * sizeof(float4);   // 64 KB dynamic tile
    cudaFuncSetAttribute(gather_kernel,
                         cudaFuncAttributeMaxDynamicSharedMemorySize, smem);

    build_inv_kernel<<<((n + 3) / 4 + 255) / 256, 256>>>(coords, n);
    gather_kernel<<<BB * XX * 4, 512, smem>>>(feats, out);
}